// round 2
// baseline (speedup 1.0000x reference)
#include <cuda_runtime.h>
#include <math.h>
#include <stdint.h>

// Problem constants (GridPool, N=300000, B=4, C_IN=64, C_OUT=128, M=128, GRID=0.5)
#define NPTS   300000
#define CIN    64
#define COUT   128
#define NSCN   4
#define MDIM   128
#define KSIZE  (NSCN*MDIM*MDIM*MDIM)   // 8,388,608
#define GRIDSZ 0.5f
#define BN_EPS 1e-5f

#define SCAN_BLK   256
#define SCAN_ITEMS 16
#define SCAN_CHUNK (SCAN_BLK*SCAN_ITEMS)        // 4096
#define SCAN_NB    (KSIZE/SCAN_CHUNK)           // 2048

// ---------------- scratch (device globals — no cudaMalloc allowed) ----------
__device__ float    g_x[(size_t)NPTS*COUT];     // fc output
__device__ int      g_vkey[NPTS];
__device__ int      g_cluster[NPTS];
__device__ unsigned g_pres[KSIZE];              // presence bitmap
__device__ int      g_rank[KSIZE];              // exclusive scan of presence
__device__ unsigned g_startbits[NSCN*3];        // per-scene min coord (float bits)
__device__ float    g_colsum[COUT];
__device__ float    g_colsq[COUT];
__device__ float    g_bnA[COUT];                // y = A*x + B  (BN folded)
__device__ float    g_bnB[COUT];
__device__ unsigned g_bsums[SCAN_NB];
__device__ unsigned g_boffs[SCAN_NB];

// ---------------- helpers ----------------------------------------------------
__device__ __forceinline__ int point_batch(int i, int o0, int o1, int o2) {
    return (i >= o0) + (i >= o1) + (i >= o2);
}

__device__ unsigned block_exscan256(unsigned v) {
    unsigned lane = threadIdx.x & 31, wid = threadIdx.x >> 5;
    unsigned x = v;
    #pragma unroll
    for (int o = 1; o < 32; o <<= 1) {
        unsigned y = __shfl_up_sync(0xffffffffu, x, o);
        if (lane >= o) x += y;
    }
    __shared__ unsigned ws[8];
    if (lane == 31) ws[wid] = x;
    __syncthreads();
    unsigned woff = 0;
    #pragma unroll
    for (unsigned w = 0; w < 8; w++) woff += (w < wid) ? ws[w] : 0u;
    return woff + x - v;   // exclusive prefix of v
}

// ---------------- kernels ----------------------------------------------------
// per-scene min coordinate (segment_csr min). coords >= 0 so uint-bit atomicMin works.
__global__ void k_scene_min(const float* __restrict__ coord,
                            const int* __restrict__ offset, int n) {
    __shared__ unsigned smin[NSCN*3];
    if (threadIdx.x < NSCN*3) smin[threadIdx.x] = 0xFFFFFFFFu;
    __syncthreads();
    int o0 = offset[0], o1 = offset[1], o2 = offset[2];
    for (int i = blockIdx.x*blockDim.x + threadIdx.x; i < n; i += gridDim.x*blockDim.x) {
        int b = point_batch(i, o0, o1, o2);
        #pragma unroll
        for (int d = 0; d < 3; d++)
            atomicMin(&smin[b*3+d], __float_as_uint(coord[(size_t)i*3+d]));
    }
    __syncthreads();
    if (threadIdx.x < NSCN*3) atomicMin(&g_startbits[threadIdx.x], smin[threadIdx.x]);
}

// voxel key per point + presence mark
__global__ void k_vkey(const float* __restrict__ coord,
                       const int* __restrict__ offset, int n) {
    int i = blockIdx.x*blockDim.x + threadIdx.x;
    if (i >= n) return;
    int o0 = offset[0], o1 = offset[1], o2 = offset[2];
    int b = point_batch(i, o0, o1, o2);
    float sx = __uint_as_float(g_startbits[b*3+0]);
    float sy = __uint_as_float(g_startbits[b*3+1]);
    float sz = __uint_as_float(g_startbits[b*3+2]);
    int vx = (int)floorf((coord[(size_t)i*3+0] - sx) / GRIDSZ);
    int vy = (int)floorf((coord[(size_t)i*3+1] - sy) / GRIDSZ);
    int vz = (int)floorf((coord[(size_t)i*3+2] - sz) / GRIDSZ);
    int key = ((b*MDIM + vx)*MDIM + vy)*MDIM + vz;
    g_vkey[i] = key;
    g_pres[key] = 1u;
}

// scan pass 1: per-block sums over 4096-element chunks
__global__ void k_scan1() {
    int base = blockIdx.x*SCAN_CHUNK + threadIdx.x*SCAN_ITEMS;
    const uint4* p = (const uint4*)&g_pres[base];
    unsigned s = 0;
    #pragma unroll
    for (int j = 0; j < SCAN_ITEMS/4; j++) { uint4 v = p[j]; s += v.x+v.y+v.z+v.w; }
    __shared__ unsigned red[SCAN_BLK];
    red[threadIdx.x] = s; __syncthreads();
    for (int st = SCAN_BLK/2; st > 0; st >>= 1) {
        if (threadIdx.x < st) red[threadIdx.x] += red[threadIdx.x+st];
        __syncthreads();
    }
    if (threadIdx.x == 0) g_bsums[blockIdx.x] = red[0];
}

// scan pass 2: exclusive scan of the 2048 block sums (single block)
__global__ void k_scan2() {
    int t = threadIdx.x;
    unsigned v[SCAN_NB/SCAN_BLK];           // 8
    unsigned s = 0;
    #pragma unroll
    for (int j = 0; j < SCAN_NB/SCAN_BLK; j++) { v[j] = g_bsums[t*(SCAN_NB/SCAN_BLK)+j]; s += v[j]; }
    unsigned run = block_exscan256(s);
    #pragma unroll
    for (int j = 0; j < SCAN_NB/SCAN_BLK; j++) { g_boffs[t*(SCAN_NB/SCAN_BLK)+j] = run; run += v[j]; }
}

// scan pass 3: full exclusive scan -> g_rank
__global__ void k_scan3() {
    int base = blockIdx.x*SCAN_CHUNK + threadIdx.x*SCAN_ITEMS;
    unsigned v[SCAN_ITEMS];
    const uint4* p = (const uint4*)&g_pres[base];
    unsigned s = 0;
    #pragma unroll
    for (int j = 0; j < SCAN_ITEMS/4; j++) {
        uint4 q = p[j];
        v[j*4+0]=q.x; v[j*4+1]=q.y; v[j*4+2]=q.z; v[j*4+3]=q.w;
        s += q.x+q.y+q.z+q.w;
    }
    unsigned run = block_exscan256(s) + g_boffs[blockIdx.x];
    #pragma unroll
    for (int j = 0; j < SCAN_ITEMS; j++) { g_rank[base+j] = (int)run; run += v[j]; }
}

// fp32 GEMM: x[n,128] = feat[n,64] @ W[64,128]; 128x128 tile, 8x8 microtile
__global__ void k_gemm(const float* __restrict__ feat, const float* __restrict__ Wm, int n) {
    extern __shared__ float sm[];
    float* As = sm;                 // 128 x 65 (padded)
    float* Bs = sm + 128*65;        // 64 x 128
    int row0 = blockIdx.x*128;

    for (int t = threadIdx.x; t < 128*64; t += 256) {
        int r = t >> 6, c = t & 63;
        int gr = row0 + r;
        As[r*65+c] = (gr < n) ? feat[(size_t)gr*CIN + c] : 0.f;
    }
    {
        float4* B4 = (float4*)Bs;
        const float4* W4 = (const float4*)Wm;
        for (int t = threadIdx.x; t < (CIN*COUT)/4; t += 256) B4[t] = W4[t];
    }
    __syncthreads();

    int tx = threadIdx.x & 15, ty = threadIdx.x >> 4;
    float acc[8][8];
    #pragma unroll
    for (int i = 0; i < 8; i++)
        #pragma unroll
        for (int j = 0; j < 8; j++) acc[i][j] = 0.f;

    #pragma unroll 8
    for (int k = 0; k < CIN; k++) {
        float ra[8], rb[8];
        #pragma unroll
        for (int i = 0; i < 8; i++) ra[i] = As[(16*i+ty)*65 + k];
        #pragma unroll
        for (int j = 0; j < 8; j++) rb[j] = Bs[k*COUT + 16*j+tx];
        #pragma unroll
        for (int i = 0; i < 8; i++)
            #pragma unroll
            for (int j = 0; j < 8; j++) acc[i][j] += ra[i]*rb[j];
    }
    #pragma unroll
    for (int i = 0; i < 8; i++) {
        int gr = row0 + 16*i + ty;
        if (gr < n) {
            #pragma unroll
            for (int j = 0; j < 8; j++)
                g_x[(size_t)gr*COUT + 16*j+tx] = acc[i][j];
        }
    }
}

// per-column sum / sumsq
__global__ void k_colstats(int n) {
    int j = threadIdx.x;            // 128 threads
    float s = 0.f, q = 0.f;
    for (int r = blockIdx.x; r < n; r += gridDim.x) {
        float v = g_x[(size_t)r*COUT + j];
        s += v; q += v*v;
    }
    atomicAdd(&g_colsum[j], s);
    atomicAdd(&g_colsq[j], q);
}

// fold BN into y = A*x + B
__global__ void k_meanvar(const float* __restrict__ gamma,
                          const float* __restrict__ beta, int n) {
    int j = threadIdx.x;
    float inv_n = 1.f / (float)n;
    float mean = g_colsum[j] * inv_n;
    float var  = g_colsq[j] * inv_n - mean*mean;
    float inv  = rsqrtf(var + BN_EPS);
    float a = gamma[j] * inv;
    g_bnA[j] = a;
    g_bnB[j] = beta[j] - a*mean;
}

// fill batch_out with int32-max identity (segment_min of empty segments)
__global__ void k_fillbatch(float* oBatch, int n) {
    int i = blockIdx.x*blockDim.x + threadIdx.x;
    if (i < n) oBatch[i] = 2147483648.0f;   // (float)INT32_MAX
}

// per-point scatter: cluster id, coord sums, counts, batch
__global__ void k_scatter(const float* __restrict__ coord,
                          const int* __restrict__ offset,
                          float* oCoord, float* oClus, float* oCnt, float* oBatch, int n) {
    int i = blockIdx.x*blockDim.x + threadIdx.x;
    if (i >= n) return;
    int c = g_rank[g_vkey[i]];
    g_cluster[i] = c;
    oClus[i] = (float)c;
    atomicAdd(&oCoord[(size_t)c*3+0], coord[(size_t)i*3+0]);
    atomicAdd(&oCoord[(size_t)c*3+1], coord[(size_t)i*3+1]);
    atomicAdd(&oCoord[(size_t)c*3+2], coord[(size_t)i*3+2]);
    atomicAdd(&oCnt[c], 1.0f);
    int o0 = offset[0], o1 = offset[1], o2 = offset[2];
    oBatch[c] = (float)point_batch(i, o0, o1, o2);   // benign same-value race
}

// segment max of BN+ReLU features (values >= 0 -> uint-bit atomicMax, 0-init)
__global__ void k_featmax(float* oFeat, int n) {
    int idx = blockIdx.x*blockDim.x + threadIdx.x;
    if (idx >= n*COUT) return;
    int i = idx >> 7, j = idx & 127;
    float y = g_bnA[j]*g_x[idx] + g_bnB[j];
    if (y > 0.f) {
        int c = g_cluster[i];
        atomicMax((unsigned*)&oFeat[(size_t)c*COUT + j], __float_as_uint(y));
    }
}

// coord_out = sum / max(count,1)
__global__ void k_fincoord(float* oCoord, const float* oCnt, int n) {
    int i = blockIdx.x*blockDim.x + threadIdx.x;
    if (i >= n) return;
    float d = 1.f / fmaxf(oCnt[i], 1.f);
    oCoord[(size_t)i*3+0] *= d;
    oCoord[(size_t)i*3+1] *= d;
    oCoord[(size_t)i*3+2] *= d;
}

// ---------------- launch -----------------------------------------------------
extern "C" void kernel_launch(void* const* d_in, const int* in_sizes, int n_in,
                              void* d_out, int out_size) {
    const float* coord  = (const float*)d_in[0];
    const float* feat   = (const float*)d_in[1];
    const int*   offset = (const int*)  d_in[2];
    const float* Wm     = (const float*)d_in[3];
    const float* gamma  = (const float*)d_in[4];
    const float* beta   = (const float*)d_in[5];
    const int n = in_sizes[0] / 3;

    float* out    = (float*)d_out;
    float* oCoord = out;
    float* oFeat  = out + (size_t)3*n;
    float* oClus  = out + (size_t)131*n;
    float* oCnt   = out + (size_t)132*n;
    float* oBatch = out + (size_t)133*n;

    void *pPres, *pStart, *pColsum, *pColsq;
    cudaGetSymbolAddress(&pPres,   g_pres);
    cudaGetSymbolAddress(&pStart,  g_startbits);
    cudaGetSymbolAddress(&pColsum, g_colsum);
    cudaGetSymbolAddress(&pColsq,  g_colsq);

    // resets (graph-capturable async memsets)
    cudaMemsetAsync(pPres,   0,    (size_t)KSIZE*4);
    cudaMemsetAsync(pStart,  0xFF, NSCN*3*4);
    cudaMemsetAsync(pColsum, 0,    COUT*4);
    cudaMemsetAsync(pColsq,  0,    COUT*4);
    cudaMemsetAsync(oCoord,  0,    (size_t)3*n*4);
    cudaMemsetAsync(oFeat,   0,    (size_t)n*COUT*4);
    cudaMemsetAsync(oCnt,    0,    (size_t)n*4);

    int tpb = 256;
    int nb  = (n + tpb - 1) / tpb;

    k_scene_min<<<512, tpb>>>(coord, offset, n);
    k_vkey<<<nb, tpb>>>(coord, offset, n);
    k_scan1<<<SCAN_NB, SCAN_BLK>>>();
    k_scan2<<<1, SCAN_BLK>>>();
    k_scan3<<<SCAN_NB, SCAN_BLK>>>();

    static bool attr_set = false;
    size_t smem = (128*65 + 64*128) * sizeof(float);   // 66 KB
    if (!attr_set) {
        cudaFuncSetAttribute(k_gemm, cudaFuncAttributeMaxDynamicSharedMemorySize, (int)smem);
        attr_set = true;
    }
    k_gemm<<<(n + 127)/128, 256, smem>>>(feat, Wm, n);
    k_colstats<<<1024, COUT>>>(n);
    k_meanvar<<<1, COUT>>>(gamma, beta, n);

    k_fillbatch<<<nb, tpb>>>(oBatch, n);
    k_scatter<<<nb, tpb>>>(coord, offset, oCoord, oClus, oCnt, oBatch, n);
    k_featmax<<<((size_t)n*COUT + tpb - 1)/tpb, tpb>>>(oFeat, n);
    k_fincoord<<<nb, tpb>>>(oCoord, oCnt, n);
}

// round 3
// speedup vs baseline: 1.7931x; 1.7931x over previous
#include <cuda_runtime.h>
#include <math.h>
#include <stdint.h>

// Problem constants (GridPool, N=300000, B=4, C_IN=64, C_OUT=128, M=128, GRID=0.5)
#define NPTS   300000
#define CIN    64
#define COUT   128
#define NSCN   4
#define MDIM   128
#define KSIZE  (NSCN*MDIM*MDIM*MDIM)   // 8,388,608 keys
#define NWORDS (KSIZE/32)              // 262,144 bitmap words
#define GRIDSZ 0.5f
#define BN_EPS 1e-5f

// bit-scan geometry: 64 blocks x 256 threads x 16 words
#define BS_BLK   256
#define BS_ITEMS 16
#define BS_CHUNK (BS_BLK*BS_ITEMS)     // 4096 words
#define BS_NB    (NWORDS/BS_CHUNK)     // 64

// count-scan geometry over NPTS cluster slots
#define CS_CHUNK 4096
#define CS_NB    ((NPTS + CS_CHUNK - 1)/CS_CHUNK)   // 74

// ---------------- scratch (device globals) -----------------------------------
__device__ float    g_x[(size_t)NPTS*COUT];     // fc output
__device__ int      g_vkey[NPTS];
__device__ int      g_cluster[NPTS];
__device__ unsigned g_bits[NWORDS];             // presence bitmap (1 bit/key)
__device__ int      g_wordrank[NWORDS];         // exclusive popcount scan per word
__device__ int      g_ncl;                      // total cluster count
__device__ unsigned g_startbits[NSCN*3];        // per-scene min coord (float bits)
__device__ float    g_colsum[COUT];
__device__ float    g_colsq[COUT];
__device__ float    g_bnA[COUT];                // y = A*x + B  (BN folded)
__device__ float    g_bnB[COUT];
__device__ unsigned g_bsums[BS_NB];
__device__ unsigned g_boffs[BS_NB];
__device__ int      g_ccnt[NPTS];               // per-cluster point count
__device__ int      g_cstart[NPTS];             // per-cluster start (mutated to end by fill)
__device__ int      g_csums[CS_NB];
__device__ int      g_coffs[CS_NB];
__device__ int      g_plist[NPTS];              // point indices grouped by cluster

// ---------------- helpers ----------------------------------------------------
__device__ __forceinline__ int point_batch(int i, int o0, int o1, int o2) {
    return (i >= o0) + (i >= o1) + (i >= o2);
}

template<typename T>
__device__ T block_exscan256(T v) {           // requires 256 threads
    unsigned lane = threadIdx.x & 31, wid = threadIdx.x >> 5;
    T x = v;
    #pragma unroll
    for (int o = 1; o < 32; o <<= 1) {
        T y = __shfl_up_sync(0xffffffffu, x, o);
        if (lane >= o) x += y;
    }
    __shared__ T ws[8];
    if (lane == 31) ws[wid] = x;
    __syncthreads();
    T woff = 0;
    #pragma unroll
    for (unsigned w = 0; w < 8; w++) woff += (w < wid) ? ws[w] : (T)0;
    __syncthreads();
    return woff + x - v;   // exclusive prefix of v
}

// ---------------- kernels ----------------------------------------------------
// per-scene min coordinate. coords >= 0 so uint-bit atomicMin works.
__global__ void k_scene_min(const float* __restrict__ coord,
                            const int* __restrict__ offset, int n) {
    __shared__ unsigned smin[NSCN*3];
    if (threadIdx.x < NSCN*3) smin[threadIdx.x] = 0xFFFFFFFFu;
    __syncthreads();
    int o0 = offset[0], o1 = offset[1], o2 = offset[2];
    for (int i = blockIdx.x*blockDim.x + threadIdx.x; i < n; i += gridDim.x*blockDim.x) {
        int b = point_batch(i, o0, o1, o2);
        #pragma unroll
        for (int d = 0; d < 3; d++)
            atomicMin(&smin[b*3+d], __float_as_uint(coord[(size_t)i*3+d]));
    }
    __syncthreads();
    if (threadIdx.x < NSCN*3) atomicMin(&g_startbits[threadIdx.x], smin[threadIdx.x]);
}

// voxel key per point + presence bit
__global__ void k_vkey(const float* __restrict__ coord,
                       const int* __restrict__ offset, int n) {
    int i = blockIdx.x*blockDim.x + threadIdx.x;
    if (i >= n) return;
    int o0 = offset[0], o1 = offset[1], o2 = offset[2];
    int b = point_batch(i, o0, o1, o2);
    float sx = __uint_as_float(g_startbits[b*3+0]);
    float sy = __uint_as_float(g_startbits[b*3+1]);
    float sz = __uint_as_float(g_startbits[b*3+2]);
    int vx = (int)floorf((coord[(size_t)i*3+0] - sx) / GRIDSZ);
    int vy = (int)floorf((coord[(size_t)i*3+1] - sy) / GRIDSZ);
    int vz = (int)floorf((coord[(size_t)i*3+2] - sz) / GRIDSZ);
    int key = ((b*MDIM + vx)*MDIM + vy)*MDIM + vz;
    g_vkey[i] = key;
    atomicOr(&g_bits[key >> 5], 1u << (key & 31));
}

// bit-scan pass 1: popcount sums per 4096-word chunk
__global__ void b_scan1() {
    int base = blockIdx.x*BS_CHUNK + threadIdx.x*BS_ITEMS;
    const uint4* p = (const uint4*)&g_bits[base];
    unsigned s = 0;
    #pragma unroll
    for (int j = 0; j < BS_ITEMS/4; j++) {
        uint4 v = p[j];
        s += __popc(v.x)+__popc(v.y)+__popc(v.z)+__popc(v.w);
    }
    __shared__ unsigned red[BS_BLK];
    red[threadIdx.x] = s; __syncthreads();
    for (int st = BS_BLK/2; st > 0; st >>= 1) {
        if (threadIdx.x < st) red[threadIdx.x] += red[threadIdx.x+st];
        __syncthreads();
    }
    if (threadIdx.x == 0) g_bsums[blockIdx.x] = red[0];
}

// bit-scan pass 2: exclusive scan of 64 block sums (single warp) + total
__global__ void b_scan2() {
    int t = threadIdx.x;                 // 32 threads
    unsigned v0 = g_bsums[2*t], v1 = g_bsums[2*t+1];
    unsigned s = v0 + v1, x = s;
    #pragma unroll
    for (int o = 1; o < 32; o <<= 1) {
        unsigned y = __shfl_up_sync(0xffffffffu, x, o);
        if (t >= o) x += y;
    }
    unsigned e = x - s;                  // exclusive
    g_boffs[2*t]   = e;
    g_boffs[2*t+1] = e + v0;
    if (t == 31) g_ncl = (int)(e + s);
}

// bit-scan pass 3: per-word exclusive rank
__global__ void b_scan3() {
    int base = blockIdx.x*BS_CHUNK + threadIdx.x*BS_ITEMS;
    unsigned pc[BS_ITEMS];
    const uint4* p = (const uint4*)&g_bits[base];
    unsigned s = 0;
    #pragma unroll
    for (int j = 0; j < BS_ITEMS/4; j++) {
        uint4 q = p[j];
        pc[j*4+0]=__popc(q.x); pc[j*4+1]=__popc(q.y);
        pc[j*4+2]=__popc(q.z); pc[j*4+3]=__popc(q.w);
        s += pc[j*4+0]+pc[j*4+1]+pc[j*4+2]+pc[j*4+3];
    }
    unsigned run = block_exscan256<unsigned>(s) + g_boffs[blockIdx.x];
    #pragma unroll
    for (int j = 0; j < BS_ITEMS; j++) { g_wordrank[base+j] = (int)run; run += pc[j]; }
}

// fp32 GEMM with fused column sum/sumsq epilogue
__global__ void k_gemm(const float* __restrict__ feat, const float* __restrict__ Wm, int n) {
    extern __shared__ float sm[];
    float* As = sm;                 // 128 x 65 (padded)
    float* Bs = sm + 128*65;        // 64 x 128
    int row0 = blockIdx.x*128;

    for (int t = threadIdx.x; t < 128*64; t += 256) {
        int r = t >> 6, c = t & 63;
        int gr = row0 + r;
        As[r*65+c] = (gr < n) ? feat[(size_t)gr*CIN + c] : 0.f;
    }
    {
        float4* B4 = (float4*)Bs;
        const float4* W4 = (const float4*)Wm;
        for (int t = threadIdx.x; t < (CIN*COUT)/4; t += 256) B4[t] = W4[t];
    }
    __syncthreads();

    int tx = threadIdx.x & 15, ty = threadIdx.x >> 4;
    float acc[8][8];
    #pragma unroll
    for (int i = 0; i < 8; i++)
        #pragma unroll
        for (int j = 0; j < 8; j++) acc[i][j] = 0.f;

    #pragma unroll 8
    for (int k = 0; k < CIN; k++) {
        float ra[8], rb[8];
        #pragma unroll
        for (int i = 0; i < 8; i++) ra[i] = As[(16*i+ty)*65 + k];
        #pragma unroll
        for (int j = 0; j < 8; j++) rb[j] = Bs[k*COUT + 16*j+tx];
        #pragma unroll
        for (int i = 0; i < 8; i++)
            #pragma unroll
            for (int j = 0; j < 8; j++) acc[i][j] += ra[i]*rb[j];
    }
    #pragma unroll
    for (int i = 0; i < 8; i++) {
        int gr = row0 + 16*i + ty;
        if (gr < n) {
            #pragma unroll
            for (int j = 0; j < 8; j++)
                g_x[(size_t)gr*COUT + 16*j+tx] = acc[i][j];
        }
    }

    // fused column stats: rows beyond n contribute 0 (As zero-padded)
    __syncthreads();                // done reading As/Bs
    float* rsum = sm;               // 128 cols x 16 ty
    float* rsq  = sm + 2048;
    #pragma unroll
    for (int j = 0; j < 8; j++) {
        float s = 0.f, q = 0.f;
        #pragma unroll
        for (int i = 0; i < 8; i++) { float v = acc[i][j]; s += v; q += v*v; }
        rsum[(16*j+tx)*16 + ty] = s;
        rsq [(16*j+tx)*16 + ty] = q;
    }
    __syncthreads();
    if (threadIdx.x < COUT) {
        float s = 0.f, q = 0.f;
        #pragma unroll
        for (int t = 0; t < 16; t++) { s += rsum[threadIdx.x*16+t]; q += rsq[threadIdx.x*16+t]; }
        atomicAdd(&g_colsum[threadIdx.x], s);
        atomicAdd(&g_colsq[threadIdx.x], q);
    }
}

// fold BN into y = A*x + B
__global__ void k_meanvar(const float* __restrict__ gamma,
                          const float* __restrict__ beta, int n) {
    int j = threadIdx.x;
    float inv_n = 1.f / (float)n;
    float mean = g_colsum[j] * inv_n;
    float var  = g_colsq[j] * inv_n - mean*mean;
    float inv  = rsqrtf(var + BN_EPS);
    float a = gamma[j] * inv;
    g_bnA[j] = a;
    g_bnB[j] = beta[j] - a*mean;
}

// cluster id per point (rank via bitmap popcount) + per-cluster counts
__global__ void k_assign(float* __restrict__ oClus, int n) {
    int i = blockIdx.x*blockDim.x + threadIdx.x;
    if (i >= n) return;
    int key = g_vkey[i];
    unsigned w = g_bits[key >> 5];
    int c = g_wordrank[key >> 5] + __popc(w & ((1u << (key & 31)) - 1u));
    g_cluster[i] = c;
    oClus[i] = (float)c;
    atomicAdd(&g_ccnt[c], 1);
}

// counting-sort scans over NPTS cluster slots
__global__ void c_scan1(int n) {
    int base = blockIdx.x*CS_CHUNK + threadIdx.x*16;
    int s = 0;
    #pragma unroll
    for (int j = 0; j < 16; j++) { int i = base+j; s += (i < n) ? g_ccnt[i] : 0; }
    __shared__ int red[256];
    red[threadIdx.x] = s; __syncthreads();
    for (int st = 128; st > 0; st >>= 1) {
        if (threadIdx.x < st) red[threadIdx.x] += red[threadIdx.x+st];
        __syncthreads();
    }
    if (threadIdx.x == 0) g_csums[blockIdx.x] = red[0];
}

__global__ void c_scan2() {                  // 1 block, 128 threads >= CS_NB
    __shared__ int s[128];
    int t = threadIdx.x;
    int v = (t < CS_NB) ? g_csums[t] : 0;
    s[t] = v; __syncthreads();
    #pragma unroll
    for (int o = 1; o < 128; o <<= 1) {
        int y = (t >= o) ? s[t-o] : 0;
        __syncthreads();
        s[t] += y;
        __syncthreads();
    }
    if (t < CS_NB) g_coffs[t] = s[t] - v;    // exclusive
}

__global__ void c_scan3(int n) {
    int base = blockIdx.x*CS_CHUNK + threadIdx.x*16;
    int v[16];
    int s = 0;
    #pragma unroll
    for (int j = 0; j < 16; j++) { int i = base+j; v[j] = (i < n) ? g_ccnt[i] : 0; s += v[j]; }
    int run = block_exscan256<int>(s) + g_coffs[blockIdx.x];
    #pragma unroll
    for (int j = 0; j < 16; j++) { int i = base+j; if (i < n) g_cstart[i] = run; run += v[j]; }
}

// fill point lists (mutates g_cstart -> segment end)
__global__ void k_fill(int n) {
    int i = blockIdx.x*blockDim.x + threadIdx.x;
    if (i >= n) return;
    int c = g_cluster[i];
    int slot = atomicAdd(&g_cstart[c], 1);
    g_plist[slot] = i;
}

// one block per cluster: feature max, coord mean, count, batch — no atomics
__global__ void k_gather(const float* __restrict__ coord,
                         const int* __restrict__ offset,
                         float* __restrict__ oCoord, float* __restrict__ oFeat,
                         float* __restrict__ oCnt, float* __restrict__ oBatch, int n) {
    int j = threadIdx.x;            // 128 threads
    int ncl = g_ncl;
    float a = g_bnA[j], bb = g_bnB[j];
    int o0 = offset[0], o1 = offset[1], o2 = offset[2];

    for (int c = blockIdx.x; c < n; c += gridDim.x) {
        if (c < ncl) {
            int cnt = g_ccnt[c];
            int end = g_cstart[c];          // start+cnt after k_fill
            int start = end - cnt;
            float m = 0.f;                  // ReLU identity
            for (int p = 0; p < cnt; p++) {
                int i = g_plist[start+p];
                float y = a * g_x[(size_t)i*COUT + j] + bb;
                m = fmaxf(m, y);
            }
            oFeat[(size_t)c*COUT + j] = m;
            if (j < 3) {
                float s = 0.f;
                for (int p = 0; p < cnt; p++) {
                    int i = g_plist[start+p];
                    s += coord[(size_t)i*3 + j];
                }
                oCoord[(size_t)c*3 + j] = s / (float)cnt;
            }
            if (j == 0) {
                oCnt[c] = (float)cnt;
                int i0 = g_plist[start];
                oBatch[c] = (float)point_batch(i0, o0, o1, o2);
            }
        } else {
            oFeat[(size_t)c*COUT + j] = 0.f;
            if (j < 3) oCoord[(size_t)c*3 + j] = 0.f;
            if (j == 0) { oCnt[c] = 0.f; oBatch[c] = 2147483648.0f; }
        }
    }
}

// ---------------- launch -----------------------------------------------------
extern "C" void kernel_launch(void* const* d_in, const int* in_sizes, int n_in,
                              void* d_out, int out_size) {
    const float* coord  = (const float*)d_in[0];
    const float* feat   = (const float*)d_in[1];
    const int*   offset = (const int*)  d_in[2];
    const float* Wm     = (const float*)d_in[3];
    const float* gamma  = (const float*)d_in[4];
    const float* beta   = (const float*)d_in[5];
    const int n = in_sizes[0] / 3;

    float* out    = (float*)d_out;
    float* oCoord = out;
    float* oFeat  = out + (size_t)3*n;
    float* oClus  = out + (size_t)131*n;
    float* oCnt   = out + (size_t)132*n;
    float* oBatch = out + (size_t)133*n;

    void *pBits, *pStart, *pColsum, *pColsq, *pCcnt;
    cudaGetSymbolAddress(&pBits,   g_bits);
    cudaGetSymbolAddress(&pStart,  g_startbits);
    cudaGetSymbolAddress(&pColsum, g_colsum);
    cudaGetSymbolAddress(&pColsq,  g_colsq);
    cudaGetSymbolAddress(&pCcnt,   g_ccnt);

    cudaMemsetAsync(pBits,   0,    (size_t)NWORDS*4);
    cudaMemsetAsync(pStart,  0xFF, NSCN*3*4);
    cudaMemsetAsync(pColsum, 0,    COUT*4);
    cudaMemsetAsync(pColsq,  0,    COUT*4);
    cudaMemsetAsync(pCcnt,   0,    (size_t)NPTS*4);

    int tpb = 256;
    int nb  = (n + tpb - 1) / tpb;

    k_scene_min<<<512, tpb>>>(coord, offset, n);
    k_vkey<<<nb, tpb>>>(coord, offset, n);
    b_scan1<<<BS_NB, BS_BLK>>>();
    b_scan2<<<1, 32>>>();
    b_scan3<<<BS_NB, BS_BLK>>>();

    static bool attr_set = false;
    size_t smem = (128*65 + 64*128) * sizeof(float);   // 66 KB
    if (!attr_set) {
        cudaFuncSetAttribute(k_gemm, cudaFuncAttributeMaxDynamicSharedMemorySize, (int)smem);
        attr_set = true;
    }
    k_gemm<<<(n + 127)/128, 256, smem>>>(feat, Wm, n);
    k_meanvar<<<1, COUT>>>(gamma, beta, n);

    k_assign<<<nb, tpb>>>(oClus, n);
    c_scan1<<<CS_NB, 256>>>(n);
    c_scan2<<<1, 128>>>();
    c_scan3<<<CS_NB, 256>>>(n);
    k_fill<<<nb, tpb>>>(n);

    k_gather<<<4096, COUT>>>(coord, offset, oCoord, oFeat, oCnt, oBatch, n);
}